// round 1
// baseline (speedup 1.0000x reference)
#include <cuda_runtime.h>
#include <cuda_bf16.h>

#define BATCHSZ 2
#define DM      384
#define DI      768
#define LSEQ    1568
#define DTR     24
#define DST     16
#define DEPTH   24
#define NPATCH  3136      // B*T*NTOK = 2*8*196
#define PKDIM   768       // 3*16*16

// ---------------- scratch (static device globals; no allocation) ----------------
__device__ float g_patches[NPATCH * PKDIM];
__device__ float g_hidden[BATCHSZ * LSEQ * DM];
__device__ float g_resid [BATCHSZ * LSEQ * DM];
__device__ float g_norm  [BATCHSZ * LSEQ * DM];
__device__ float g_xz    [BATCHSZ * 2 * DI * LSEQ];     // (b, e, l)
__device__ float g_xc    [2 * BATCHSZ * DI * LSEQ];     // (dir, b, d, p) comp order
__device__ float g_dt    [2 * BATCHSZ * DI * LSEQ];
__device__ float g_xdbl  [2 * BATCHSZ * 56 * LSEQ];
__device__ float g_btr   [2 * BATCHSZ * LSEQ * DST];    // B transposed (dirb, p, n)
__device__ float g_ctr   [2 * BATCHSZ * LSEQ * DST];
__device__ float g_ys    [2 * BATCHSZ * DI * LSEQ];
__device__ float g_ycomb [BATCHSZ * DI * LSEQ];         // (b, d, l)

// ---------------- helpers ----------------
__global__ void k_zero(float* p, int n) {
    int i = blockIdx.x * blockDim.x + threadIdx.x;
    if (i < n) p[i] = 0.f;
}

// gather patches: patches[bt*196+n, c] = x[b, ch, t, gy*16+py, gx*16+px]
__global__ void k_patch_gather(const float* __restrict__ x) {
    int idx = blockIdx.x * blockDim.x + threadIdx.x;
    if (idx >= NPATCH * PKDIM) return;
    int row = idx / PKDIM, c = idx % PKDIM;
    int b = row / 1568; int rem = row % 1568; int t = rem / 196; int n = rem % 196;
    int gy = n / 14, gx = n % 14;
    int ch = c / 256; int r = c % 256; int py = r / 16, px = r % 16;
    g_patches[idx] = x[(((long)(b * 3 + ch) * 8 + t) * 224 + gy * 16 + py) * 224 + gx * 16 + px];
}

// res += hidden; norm = rmsnorm(res)*nw   (one block per row of 384)
__global__ void k_prenorm(const float* __restrict__ nw) {
    int base = blockIdx.x * DM;
    __shared__ float red[4];
    float v[3]; float ss = 0.f;
#pragma unroll
    for (int i = 0; i < 3; i++) {
        int c = threadIdx.x + i * 128;
        float t = g_resid[base + c] + g_hidden[base + c];
        g_resid[base + c] = t; v[i] = t; ss += t * t;
    }
#pragma unroll
    for (int o = 16; o; o >>= 1) ss += __shfl_xor_sync(0xffffffffu, ss, o);
    if ((threadIdx.x & 31) == 0) red[threadIdx.x >> 5] = ss;
    __syncthreads();
    float r = rsqrtf((red[0] + red[1] + red[2] + red[3]) * (1.f / DM) + 1e-5f);
#pragma unroll
    for (int i = 0; i < 3; i++) {
        int c = threadIdx.x + i * 128;
        g_norm[base + c] = v[i] * r * nw[c];
    }
}

__global__ void k_final(const float* __restrict__ nf, float* __restrict__ out) {
    int base = blockIdx.x * DM;
    __shared__ float red[4];
    float v[3]; float ss = 0.f;
#pragma unroll
    for (int i = 0; i < 3; i++) {
        int c = threadIdx.x + i * 128;
        float t = g_resid[base + c] + g_hidden[base + c];
        v[i] = t; ss += t * t;
    }
#pragma unroll
    for (int o = 16; o; o >>= 1) ss += __shfl_xor_sync(0xffffffffu, ss, o);
    if ((threadIdx.x & 31) == 0) red[threadIdx.x >> 5] = ss;
    __syncthreads();
    float r = rsqrtf((red[0] + red[1] + red[2] + red[3]) * (1.f / DM) + 1e-5f);
#pragma unroll
    for (int i = 0; i < 3; i++) {
        int c = threadIdx.x + i * 128;
        out[base + c] = v[i] * r * nf[c];
    }
}

// ---------------- tiled GEMMs (64x64x16, 256 thr, 4x4 per thread) ----------------
// NT: C[m,n] = sum_k A[m*lda+k] * B[n*ldb+k]
// EPI 0: plain    EPI 1: patch-embed epilogue (+bias + pos + temporal pos)
template<int EPI>
__global__ void k_gemm_nt(const float* __restrict__ A, const float* __restrict__ B,
                          float* __restrict__ C, int M, int N, int K,
                          int lda, int ldb, int ldc, long sB, long sC,
                          const float* __restrict__ e0, const float* __restrict__ e1,
                          const float* __restrict__ e2) {
    const float* Bp = B + (long)blockIdx.z * sB;
    float* Cp = C + (long)blockIdx.z * sC;
    __shared__ float As[16][68];
    __shared__ float Bs[16][68];
    int m0 = blockIdx.y * 64, n0 = blockIdx.x * 64;
    int tid = threadIdx.x, tx = tid & 15, ty = tid >> 4;
    int lr = tid >> 2, lc = (tid & 3) * 4;
    float acc[4][4] = {};
    for (int k0 = 0; k0 < K; k0 += 16) {
#pragma unroll
        for (int j = 0; j < 4; j++) {
            int k = k0 + lc + j;
            int ma = m0 + lr;
            As[lc + j][lr] = (ma < M && k < K) ? A[(long)ma * lda + k] : 0.f;
            int nb = n0 + lr;
            Bs[lc + j][lr] = (nb < N && k < K) ? Bp[(long)nb * ldb + k] : 0.f;
        }
        __syncthreads();
#pragma unroll
        for (int k = 0; k < 16; k++) {
            float a[4], b[4];
#pragma unroll
            for (int i = 0; i < 4; i++) a[i] = As[k][ty * 4 + i];
#pragma unroll
            for (int j = 0; j < 4; j++) b[j] = Bs[k][tx * 4 + j];
#pragma unroll
            for (int i = 0; i < 4; i++)
#pragma unroll
                for (int j = 0; j < 4; j++) acc[i][j] = fmaf(a[i], b[j], acc[i][j]);
        }
        __syncthreads();
    }
#pragma unroll
    for (int i = 0; i < 4; i++) {
        int m = m0 + ty * 4 + i; if (m >= M) continue;
#pragma unroll
        for (int j = 0; j < 4; j++) {
            int n = n0 + tx * 4 + j; if (n >= N) continue;
            float v = acc[i][j];
            if (EPI == 1) v += e0[n] + e1[(m % 196) * DM + n] + e2[((m / 196) & 7) * DM + n];
            Cp[(long)m * ldc + n] = v;
        }
    }
}

// NN: C[m,n] = sum_k A[m*lda+k] * B[k*ldb+n]
// EPI 0: plain    EPI 2: softplus(v + e0[m])    EPI 3: transposed store C[n*ldc+m]
template<int EPI>
__global__ void k_gemm_nn(const float* __restrict__ A, const float* __restrict__ B,
                          float* __restrict__ C, int M, int N, int K,
                          int lda, int ldb, int ldc, long sB, long sC,
                          const float* __restrict__ e0) {
    const float* Bp = B + (long)blockIdx.z * sB;
    float* Cp = C + (long)blockIdx.z * sC;
    __shared__ float As[16][68];
    __shared__ float Bs[16][68];
    int m0 = blockIdx.y * 64, n0 = blockIdx.x * 64;
    int tid = threadIdx.x, tx = tid & 15, ty = tid >> 4;
    int lrA = tid >> 2, lcA = (tid & 3) * 4;
    int lrB = tid >> 4, lcB = (tid & 15) * 4;
    float acc[4][4] = {};
    for (int k0 = 0; k0 < K; k0 += 16) {
#pragma unroll
        for (int j = 0; j < 4; j++) {
            int k = k0 + lcA + j, ma = m0 + lrA;
            As[lcA + j][lrA] = (ma < M && k < K) ? A[(long)ma * lda + k] : 0.f;
        }
        {
            int kb = k0 + lrB;
#pragma unroll
            for (int j = 0; j < 4; j++) {
                int nb = n0 + lcB + j;
                Bs[lrB][lcB + j] = (kb < K && nb < N) ? Bp[(long)kb * ldb + nb] : 0.f;
            }
        }
        __syncthreads();
#pragma unroll
        for (int k = 0; k < 16; k++) {
            float a[4], b[4];
#pragma unroll
            for (int i = 0; i < 4; i++) a[i] = As[k][ty * 4 + i];
#pragma unroll
            for (int j = 0; j < 4; j++) b[j] = Bs[k][tx * 4 + j];
#pragma unroll
            for (int i = 0; i < 4; i++)
#pragma unroll
                for (int j = 0; j < 4; j++) acc[i][j] = fmaf(a[i], b[j], acc[i][j]);
        }
        __syncthreads();
    }
#pragma unroll
    for (int i = 0; i < 4; i++) {
        int m = m0 + ty * 4 + i; if (m >= M) continue;
#pragma unroll
        for (int j = 0; j < 4; j++) {
            int n = n0 + tx * 4 + j; if (n >= N) continue;
            float v = acc[i][j];
            if (EPI == 2) {
                v += e0[m];
                v = (v > 20.f) ? v : log1pf(__expf(v));
            }
            if (EPI == 3) Cp[(long)n * ldc + m] = v;
            else          Cp[(long)m * ldc + n] = v;
        }
    }
}

// ---------------- causal depthwise conv (K=4) + silu; bwd dir reads flipped ----------------
__global__ void k_conv(const float* __restrict__ cwf, const float* __restrict__ cbf,
                       const float* __restrict__ cwb, const float* __restrict__ cbb) {
    int idx = blockIdx.x * blockDim.x + threadIdx.x;
    if (idx >= DI * LSEQ) return;
    int b = blockIdx.y, dir = blockIdx.z;
    int d = idx / LSEQ, p = idx % LSEQ;
    const float* w = (dir ? cwb : cwf) + d * 4;
    float acc = (dir ? cbb : cbf)[d];
    const float* xi = g_xz + ((long)b * 2 * DI + d) * LSEQ;
#pragma unroll
    for (int k = 0; k < 4; k++) {
        int q = p - 3 + k;
        if (q >= 0) {
            int l = dir ? (LSEQ - 1 - q) : q;
            acc += w[k] * xi[l];
        }
    }
    float s = acc / (1.f + __expf(-acc));   // silu
    g_xc[(((long)dir * BATCHSZ + b) * DI + d) * LSEQ + p] = s;
}

// transpose B/C rows of xdbl into (dirb, p, n) for coalesced scan loads
__global__ void k_bc_t() {
    int idx = blockIdx.x * blockDim.x + threadIdx.x;
    if (idx >= 2 * BATCHSZ * LSEQ * DST) return;
    int n = idx & 15;
    int p = (idx >> 4) % LSEQ;
    int db = idx / (16 * LSEQ);
    long src = (long)db * 56 * LSEQ;
    g_btr[idx] = g_xdbl[src + (long)(24 + n) * LSEQ + p];
    g_ctr[idx] = g_xdbl[src + (long)(40 + n) * LSEQ + p];
}

// selective scan: one thread per (dir,b,d,n); 16-lane groups reduce over n
__global__ void k_scan(const float* __restrict__ Alog_f, const float* __restrict__ Alog_b) {
    int gid = blockIdx.x * (blockDim.x >> 4) + (threadIdx.x >> 4);
    if (gid >= 2 * BATCHSZ * DI) return;
    int n = threadIdx.x & 15;
    int dir = gid / (BATCHSZ * DI);
    int r = gid % (BATCHSZ * DI);
    int b = r / DI, d = r % DI;
    const float* al = dir ? Alog_b : Alog_f;
    float acoef = -__expf(al[d * DST + n]);
    long chan = ((long)dir * BATCHSZ + b) * DI + d;
    const float* dtp = g_dt + chan * LSEQ;
    const float* xcp = g_xc + chan * LSEQ;
    float* ysp = g_ys + chan * LSEQ;
    long bc0 = ((long)dir * BATCHSZ + b) * LSEQ * (long)DST;
    const float* btp = g_btr + bc0;
    const float* ctp = g_ctr + bc0;
    float h = 0.f;
#pragma unroll 4
    for (int p = 0; p < LSEQ; p++) {
        float dtv = dtp[p], xcv = xcp[p];
        float a = __expf(dtv * acoef);
        float u = dtv * xcv * btp[p * DST + n];
        h = fmaf(a, h, u);
        float py = h * ctp[p * DST + n];
        py += __shfl_xor_sync(0xffffffffu, py, 1);
        py += __shfl_xor_sync(0xffffffffu, py, 2);
        py += __shfl_xor_sync(0xffffffffu, py, 4);
        py += __shfl_xor_sync(0xffffffffu, py, 8);
        if (n == 0) ysp[p] = py;
    }
}

// y_total[b,d,l] = (ysf[l] + Dpf*xcf[l])*silu(z[l]) + (ysb[L-1-l] + Dpb*xcb[L-1-l])*silu(z[l])
__global__ void k_combine(const float* __restrict__ Dpf, const float* __restrict__ Dpb) {
    int idx = blockIdx.x * blockDim.x + threadIdx.x;
    if (idx >= BATCHSZ * DI * LSEQ) return;
    int l = idx % LSEQ;
    int d = (idx / LSEQ) % DI;
    int b = idx / (DI * LSEQ);
    float z = g_xz[((long)b * 2 * DI + DI + d) * LSEQ + l];
    float sg = z / (1.f + __expf(-z));
    long f = ((long)b * DI + d) * LSEQ;
    long bw = (((long)BATCHSZ + b) * DI + d) * LSEQ;
    int pb = LSEQ - 1 - l;
    float yf = g_ys[f + l] + Dpf[d] * g_xc[f + l];
    float yb = g_ys[bw + pb] + Dpb[d] * g_xc[bw + pb];
    g_ycomb[f + l] = (yf + yb) * sg;
}

// ---------------- host launch ----------------
extern "C" void kernel_launch(void* const* d_in, const int* in_sizes, int n_in,
                              void* d_out, int out_size) {
    const float* x        = (const float*)d_in[0];
    const float* patch_w  = (const float*)d_in[1];
    const float* patch_b  = (const float*)d_in[2];
    const float* pos      = (const float*)d_in[3];
    const float* temp     = (const float*)d_in[4];
    const float* in_proj  = (const float*)d_in[5];
    const float* conv_w   = (const float*)d_in[6];
    const float* conv_b   = (const float*)d_in[7];
    const float* xproj_w  = (const float*)d_in[8];
    const float* dt_w     = (const float*)d_in[9];
    const float* dt_b     = (const float*)d_in[10];
    const float* A_log    = (const float*)d_in[11];
    const float* Dp       = (const float*)d_in[12];
    const float* conv_wb  = (const float*)d_in[13];
    const float* conv_bb  = (const float*)d_in[14];
    const float* xproj_wb = (const float*)d_in[15];
    const float* dt_wb    = (const float*)d_in[16];
    const float* dt_bb    = (const float*)d_in[17];
    const float* A_logb   = (const float*)d_in[18];
    const float* Dpb      = (const float*)d_in[19];
    const float* out_proj = (const float*)d_in[20];
    const float* norm_w   = (const float*)d_in[21];
    const float* norm_f   = (const float*)d_in[22];

    float *p_patches, *p_hidden, *p_resid, *p_norm, *p_xz, *p_xc, *p_dt, *p_xdbl, *p_ycomb;
    cudaGetSymbolAddress((void**)&p_patches, g_patches);
    cudaGetSymbolAddress((void**)&p_hidden,  g_hidden);
    cudaGetSymbolAddress((void**)&p_resid,   g_resid);
    cudaGetSymbolAddress((void**)&p_norm,    g_norm);
    cudaGetSymbolAddress((void**)&p_xz,      g_xz);
    cudaGetSymbolAddress((void**)&p_xc,      g_xc);
    cudaGetSymbolAddress((void**)&p_dt,      g_dt);
    cudaGetSymbolAddress((void**)&p_xdbl,    g_xdbl);
    cudaGetSymbolAddress((void**)&p_ycomb,   g_ycomb);

    // patch embedding
    k_patch_gather<<<(NPATCH * PKDIM + 255) / 256, 256>>>(x);
    k_zero<<<(BATCHSZ * LSEQ * DM + 255) / 256, 256>>>(p_resid, BATCHSZ * LSEQ * DM);
    {
        dim3 g((DM + 63) / 64, (NPATCH + 63) / 64, 1);
        k_gemm_nt<1><<<g, 256>>>(p_patches, patch_w, p_hidden, NPATCH, DM, PKDIM,
                                 PKDIM, PKDIM, DM, 0, 0, patch_b, pos, temp);
    }

    for (int ly = 0; ly < DEPTH; ly++) {
        k_prenorm<<<BATCHSZ * LSEQ, 128>>>(norm_w + ly * DM);

        {   // in_proj: xz[b,e,l] = sum_d norm[b,l,d]*W[e,d]
            dim3 g((LSEQ + 63) / 64, (2 * DI + 63) / 64, BATCHSZ);
            k_gemm_nt<0><<<g, 256>>>(in_proj + (long)ly * 2 * DI * DM, p_norm, p_xz,
                                     2 * DI, LSEQ, DM, DM, DM, LSEQ,
                                     (long)LSEQ * DM, (long)2 * DI * LSEQ,
                                     nullptr, nullptr, nullptr);
        }

        {   // depthwise causal conv + silu (both dirs)
            dim3 g((DI * LSEQ + 255) / 256, BATCHSZ, 2);
            k_conv<<<g, 256>>>(conv_w + (long)ly * DI * 4, conv_b + (long)ly * DI,
                               conv_wb + (long)ly * DI * 4, conv_bb + (long)ly * DI);
        }

        for (int dir = 0; dir < 2; dir++) {
            const float* xpw = (dir ? xproj_wb : xproj_w) + (long)ly * 56 * DI;
            {
                dim3 g((LSEQ + 63) / 64, 1, BATCHSZ);
                k_gemm_nn<0><<<g, 256>>>(xpw, p_xc + (long)dir * BATCHSZ * DI * LSEQ,
                                         p_xdbl + (long)dir * BATCHSZ * 56 * LSEQ,
                                         56, LSEQ, DI, DI, LSEQ, LSEQ,
                                         (long)DI * LSEQ, (long)56 * LSEQ, nullptr);
            }
            const float* dw = (dir ? dt_wb : dt_w) + (long)ly * DI * DTR;
            const float* db = (dir ? dt_bb : dt_b) + (long)ly * DI;
            {
                dim3 g((LSEQ + 63) / 64, (DI + 63) / 64, BATCHSZ);
                k_gemm_nn<2><<<g, 256>>>(dw, p_xdbl + (long)dir * BATCHSZ * 56 * LSEQ,
                                         p_dt + (long)dir * BATCHSZ * DI * LSEQ,
                                         DI, LSEQ, DTR, DTR, LSEQ, LSEQ,
                                         (long)56 * LSEQ, (long)DI * LSEQ, db);
            }
        }

        k_bc_t<<<(2 * BATCHSZ * LSEQ * DST + 255) / 256, 256>>>();
        k_scan<<<(2 * BATCHSZ * DI) / 16, 256>>>(A_log + (long)ly * DI * DST,
                                                 A_logb + (long)ly * DI * DST);
        k_combine<<<(BATCHSZ * DI * LSEQ + 255) / 256, 256>>>(Dp + (long)ly * DI,
                                                              Dpb + (long)ly * DI);

        {   // out_proj: hidden[b,l,o] = sum_d y[b,d,l]*W[o,d]  (transposed store)
            dim3 g((LSEQ + 63) / 64, (DM + 63) / 64, BATCHSZ);
            k_gemm_nn<3><<<g, 256>>>(out_proj + (long)ly * DM * DI, p_ycomb, p_hidden,
                                     DM, LSEQ, DI, DI, LSEQ, DM,
                                     (long)DI * LSEQ, (long)LSEQ * DM, nullptr);
        }
    }

    k_final<<<BATCHSZ * LSEQ, 128>>>(norm_f, (float*)d_out);
}

// round 2
// speedup vs baseline: 1.2339x; 1.2339x over previous
#include <cuda_runtime.h>

#define BATCHSZ 2
#define DM      384
#define DI      768
#define LSEQ    1568
#define LTOT    3136      // BATCH * LSEQ
#define DTR     24
#define DST     16
#define DEPTH   24
#define NPATCH  3136
#define PKDIM   768

// ---------------- scratch ----------------
__device__ float g_patches[NPATCH * PKDIM];
__device__ float g_hidden [LTOT * DM];
__device__ float g_resid  [LTOT * DM];
__device__ float g_norm   [LTOT * DM];
__device__ float g_xz     [2 * DI * LTOT];          // (e, bl)
__device__ float g_xc     [2 * DI * LTOT];          // (dir*DI+d, bl)
__device__ float g_dt     [2 * DI * LTOT];
__device__ float g_xpart  [2 * 4 * 56 * LTOT];      // split-K partials
__device__ float g_xdbl   [2 * 56 * LTOT];
__device__ float g_btr    [2 * BATCHSZ * LSEQ * DST];
__device__ float g_ctr    [2 * BATCHSZ * LSEQ * DST];
__device__ float g_ys     [2 * DI * LTOT];
__device__ float g_ycomb  [DI * LTOT];

__global__ void k_zero(float* p, int n) {
    int i = blockIdx.x * blockDim.x + threadIdx.x;
    if (i < n) p[i] = 0.f;
}

__global__ void k_patch_gather(const float* __restrict__ x) {
    int idx = blockIdx.x * blockDim.x + threadIdx.x;
    if (idx >= NPATCH * PKDIM) return;
    int row = idx / PKDIM, c = idx % PKDIM;
    int b = row / 1568; int rem = row % 1568; int t = rem / 196; int n = rem % 196;
    int gy = n / 14, gx = n % 14;
    int ch = c / 256; int r = c % 256; int py = r / 16, px = r % 16;
    g_patches[idx] = x[(((long)(b * 3 + ch) * 8 + t) * 224 + gy * 16 + py) * 224 + gx * 16 + px];
}

// res += hidden; norm = rmsnorm(res)*nw
__global__ void k_prenorm(const float* __restrict__ nw) {
    int base = blockIdx.x * DM;
    __shared__ float red[4];
    float v[3]; float ss = 0.f;
#pragma unroll
    for (int i = 0; i < 3; i++) {
        int c = threadIdx.x + i * 128;
        float t = g_resid[base + c] + g_hidden[base + c];
        g_resid[base + c] = t; v[i] = t; ss += t * t;
    }
#pragma unroll
    for (int o = 16; o; o >>= 1) ss += __shfl_xor_sync(0xffffffffu, ss, o);
    if ((threadIdx.x & 31) == 0) red[threadIdx.x >> 5] = ss;
    __syncthreads();
    float r = rsqrtf((red[0] + red[1] + red[2] + red[3]) * (1.f / DM) + 1e-5f);
#pragma unroll
    for (int i = 0; i < 3; i++) {
        int c = threadIdx.x + i * 128;
        g_norm[base + c] = v[i] * r * nw[c];
    }
}

__global__ void k_final(const float* __restrict__ nf, float* __restrict__ out) {
    int base = blockIdx.x * DM;
    __shared__ float red[4];
    float v[3]; float ss = 0.f;
#pragma unroll
    for (int i = 0; i < 3; i++) {
        int c = threadIdx.x + i * 128;
        float t = g_resid[base + c] + g_hidden[base + c];
        v[i] = t; ss += t * t;
    }
#pragma unroll
    for (int o = 16; o; o >>= 1) ss += __shfl_xor_sync(0xffffffffu, ss, o);
    if ((threadIdx.x & 31) == 0) red[threadIdx.x >> 5] = ss;
    __syncthreads();
    float r = rsqrtf((red[0] + red[1] + red[2] + red[3]) * (1.f / DM) + 1e-5f);
#pragma unroll
    for (int i = 0; i < 3; i++) {
        int c = threadIdx.x + i * 128;
        out[base + c] = v[i] * r * nf[c];
    }
}

// ---------------- GEMM: BMx64x16 tile, 256 thr, TMx4 per thread, double-buffered ----
// A: [M,K] row-major (k contiguous). B: TB=1 -> [N,K]; TB=0 -> [K,N].
// EPI 0: C[m*ldc+n]
// EPI 1: transposed C[n*ldc+m], + patch-embed adds (e0 bias, e1 pos, e2 temp)
// EPI 2: C[m*ldc+n] = softplus(v + e0[m])
// EPI 3: transposed C[n*ldc+m]
template<int BM, int TB, int EPI>
__global__ void __launch_bounds__(256)
k_gemm(const float* __restrict__ A, const float* __restrict__ B,
       float* __restrict__ C, int M, int N, int K,
       int lda, int ldb, int ldc,
       long zA, long zB, long zC,
       const float* __restrict__ e0, const float* __restrict__ e1,
       const float* __restrict__ e2)
{
    constexpr int TM = BM / 16;
    constexpr int AV = BM / 64;
    __shared__ float As[2][16][BM + 4];
    __shared__ float Bs[2][16][68];
    A += blockIdx.z * zA; B += blockIdx.z * zB; C += blockIdx.z * zC;
    const int m0 = blockIdx.y * BM, n0 = blockIdx.x * 64;
    const int tid = threadIdx.x, tx = tid & 15, ty = tid >> 4;
    const int arow = tid >> 2, akc = (tid & 3) * 4;   // A-pattern (also TB=1 B)
    const int bkr = tid >> 4, bnc = (tid & 15) * 4;   // TB=0 B-pattern

    float4 pa[AV], pb;

    auto fetch = [&](int k0) {
#pragma unroll
        for (int i = 0; i < AV; i++) {
            int row = arow + i * 64;
            int m = m0 + row, k = k0 + akc;
            pa[i] = (m < M && k < K) ? *(const float4*)(A + (long)m * lda + k)
                                     : make_float4(0.f, 0.f, 0.f, 0.f);
        }
        if (TB) {
            int n = n0 + arow, k = k0 + akc;
            pb = (k < K) ? *(const float4*)(B + (long)n * ldb + k)
                         : make_float4(0.f, 0.f, 0.f, 0.f);
        } else {
            int k = k0 + bkr;
            pb = (k < K) ? *(const float4*)(B + (long)k * ldb + n0 + bnc)
                         : make_float4(0.f, 0.f, 0.f, 0.f);
        }
    };
    auto stage = [&](int s) {
#pragma unroll
        for (int i = 0; i < AV; i++) {
            int row = arow + i * 64;
            As[s][akc + 0][row] = pa[i].x; As[s][akc + 1][row] = pa[i].y;
            As[s][akc + 2][row] = pa[i].z; As[s][akc + 3][row] = pa[i].w;
        }
        if (TB) {
            Bs[s][akc + 0][arow] = pb.x; Bs[s][akc + 1][arow] = pb.y;
            Bs[s][akc + 2][arow] = pb.z; Bs[s][akc + 3][arow] = pb.w;
        } else {
            *(float4*)&Bs[s][bkr][bnc] = pb;
        }
    };

    float acc[TM][4];
#pragma unroll
    for (int i = 0; i < TM; i++)
#pragma unroll
        for (int j = 0; j < 4; j++) acc[i][j] = 0.f;

    const int nt = (K + 15) >> 4;
    fetch(0); stage(0); __syncthreads();
    for (int t = 0; t < nt; t++) {
        int cur = t & 1;
        if (t + 1 < nt) fetch((t + 1) << 4);
#pragma unroll
        for (int k = 0; k < 16; k++) {
            float a[TM], b[4];
#pragma unroll
            for (int i = 0; i < TM / 4; i++)
                *(float4*)&a[4 * i] = *(const float4*)&As[cur][k][ty * TM + 4 * i];
            *(float4*)&b[0] = *(const float4*)&Bs[cur][k][tx * 4];
#pragma unroll
            for (int i = 0; i < TM; i++)
#pragma unroll
                for (int j = 0; j < 4; j++)
                    acc[i][j] = fmaf(a[i], b[j], acc[i][j]);
        }
        if (t + 1 < nt) stage(cur ^ 1);
        __syncthreads();
    }

    if (EPI == 0 || EPI == 2) {
#pragma unroll
        for (int i = 0; i < TM; i++) {
            int m = m0 + ty * TM + i;
            if (m >= M) continue;
            float4 v = *(float4*)&acc[i][0];
            if (EPI == 2) {
                float bb = e0[m];
                v.x += bb; v.y += bb; v.z += bb; v.w += bb;
                v.x = (v.x > 20.f) ? v.x : log1pf(__expf(v.x));
                v.y = (v.y > 20.f) ? v.y : log1pf(__expf(v.y));
                v.z = (v.z > 20.f) ? v.z : log1pf(__expf(v.z));
                v.w = (v.w > 20.f) ? v.w : log1pf(__expf(v.w));
            }
            *(float4*)(C + (long)m * ldc + n0 + tx * 4) = v;
        }
    } else {
#pragma unroll
        for (int j = 0; j < 4; j++) {
            int n = n0 + tx * 4 + j;
            float vv[TM];
#pragma unroll
            for (int i = 0; i < TM; i++) {
                float v = acc[i][j];
                if (EPI == 1) {
                    int m = m0 + ty * TM + i;
                    v += e0[m] + e1[(n % 196) * DM + m] + e2[((n / 196) & 7) * DM + m];
                }
                vv[i] = v;
            }
#pragma unroll
            for (int i = 0; i < TM / 4; i++)
                *(float4*)(C + (long)n * ldc + m0 + ty * TM + 4 * i) = *(float4*)&vv[4 * i];
        }
    }
}

// reduce split-K partials: xdbl[dir][r][n] = sum_ks xpart[dir][ks][r][n]
__global__ void k_xpred() {
    int idx = blockIdx.x * blockDim.x + threadIdx.x;
    if (idx >= 2 * 56 * LTOT) return;
    int dir = idx / (56 * LTOT);
    int r = idx % (56 * LTOT);
    long base = (long)dir * 4 * 56 * LTOT + r;
    g_xdbl[idx] = g_xpart[base] + g_xpart[base + 56 * LTOT]
                + g_xpart[base + 2L * 56 * LTOT] + g_xpart[base + 3L * 56 * LTOT];
}

// causal depthwise conv (K=4) + silu; bwd reads flipped
__global__ void k_conv(const float* __restrict__ cwf, const float* __restrict__ cbf,
                       const float* __restrict__ cwb, const float* __restrict__ cbb) {
    int idx = blockIdx.x * blockDim.x + threadIdx.x;
    if (idx >= DI * LTOT) return;
    int dir = blockIdx.y;
    int d = idx / LTOT, bl = idx % LTOT;
    int b = bl / LSEQ, p = bl % LSEQ;
    const float* w = (dir ? cwb : cwf) + d * 4;
    float acc = (dir ? cbb : cbf)[d];
    const float* xi = g_xz + (long)d * LTOT + b * LSEQ;
#pragma unroll
    for (int k = 0; k < 4; k++) {
        int q = p - 3 + k;
        if (q >= 0) acc += w[k] * xi[dir ? (LSEQ - 1 - q) : q];
    }
    g_xc[((long)dir * DI + d) * LTOT + bl] = acc / (1.f + __expf(-acc));
}

// transpose B/C rows of xdbl into (dir,b,p,n)
__global__ void k_bc_t() {
    int idx = blockIdx.x * blockDim.x + threadIdx.x;
    if (idx >= 2 * BATCHSZ * LSEQ * DST) return;
    int n = idx & 15;
    int p = (idx >> 4) % LSEQ;
    int db = idx / (16 * LSEQ);
    int dir = db >> 1, b = db & 1;
    long src = (long)dir * 56 * LTOT + b * LSEQ + p;
    g_btr[idx] = g_xdbl[src + (long)(24 + n) * LTOT];
    g_ctr[idx] = g_xdbl[src + (long)(40 + n) * LTOT];
}

// selective scan: one thread per (dir,b,d,n); 16-lane groups reduce over n
__global__ void k_scan(const float* __restrict__ Alog_f, const float* __restrict__ Alog_b) {
    int gid = blockIdx.x * (blockDim.x >> 4) + (threadIdx.x >> 4);
    if (gid >= 2 * BATCHSZ * DI) return;
    int n = threadIdx.x & 15;
    int dir = gid / (BATCHSZ * DI);
    int r = gid % (BATCHSZ * DI);
    int b = r / DI, d = r % DI;
    float acoef = -__expf((dir ? Alog_b : Alog_f)[d * DST + n]);
    long chan = ((long)dir * DI + d) * LTOT + b * LSEQ;
    const float* dtp = g_dt + chan;
    const float* xcp = g_xc + chan;
    float* ysp = g_ys + chan;
    long bc0 = ((long)dir * BATCHSZ + b) * LSEQ * (long)DST;
    const float* btp = g_btr + bc0;
    const float* ctp = g_ctr + bc0;
    float h = 0.f;
#pragma unroll 4
    for (int p = 0; p < LSEQ; p++) {
        float dtv = dtp[p], xcv = xcp[p];
        float a = __expf(dtv * acoef);
        float u = dtv * xcv * btp[p * DST + n];
        h = fmaf(a, h, u);
        float py = h * ctp[p * DST + n];
        py += __shfl_xor_sync(0xffffffffu, py, 1);
        py += __shfl_xor_sync(0xffffffffu, py, 2);
        py += __shfl_xor_sync(0xffffffffu, py, 4);
        py += __shfl_xor_sync(0xffffffffu, py, 8);
        if (n == 0) ysp[p] = py;
    }
}

__global__ void k_combine(const float* __restrict__ Dpf, const float* __restrict__ Dpb) {
    int idx = blockIdx.x * blockDim.x + threadIdx.x;
    if (idx >= DI * LTOT) return;
    int d = idx / LTOT, bl = idx % LTOT;
    int b = bl / LSEQ, l = bl % LSEQ;
    float z = g_xz[((long)DI + d) * LTOT + bl];
    float sg = z / (1.f + __expf(-z));
    long f = (long)d * LTOT + b * LSEQ;
    long bw = ((long)DI + d) * LTOT + b * LSEQ;
    int pb = LSEQ - 1 - l;
    float yf = g_ys[f + l] + Dpf[d] * g_xc[f + l];
    float yb = g_ys[bw + pb] + Dpb[d] * g_xc[bw + pb];
    g_ycomb[f + l] = (yf + yb) * sg;
}

// ---------------- host ----------------
extern "C" void kernel_launch(void* const* d_in, const int* in_sizes, int n_in,
                              void* d_out, int out_size) {
    const float* x        = (const float*)d_in[0];
    const float* patch_w  = (const float*)d_in[1];
    const float* patch_b  = (const float*)d_in[2];
    const float* pos      = (const float*)d_in[3];
    const float* temp     = (const float*)d_in[4];
    const float* in_proj  = (const float*)d_in[5];
    const float* conv_w   = (const float*)d_in[6];
    const float* conv_b   = (const float*)d_in[7];
    const float* xproj_w  = (const float*)d_in[8];
    const float* dt_w     = (const float*)d_in[9];
    const float* dt_b     = (const float*)d_in[10];
    const float* A_log    = (const float*)d_in[11];
    const float* Dp       = (const float*)d_in[12];
    const float* conv_wb  = (const float*)d_in[13];
    const float* conv_bb  = (const float*)d_in[14];
    const float* xproj_wb = (const float*)d_in[15];
    const float* dt_wb    = (const float*)d_in[16];
    const float* dt_bb    = (const float*)d_in[17];
    const float* A_logb   = (const float*)d_in[18];
    const float* Dpb      = (const float*)d_in[19];
    const float* out_proj = (const float*)d_in[20];
    const float* norm_w   = (const float*)d_in[21];
    const float* norm_f   = (const float*)d_in[22];

    float *p_patches, *p_hidden, *p_resid, *p_norm, *p_xz, *p_xc, *p_dt,
          *p_xpart, *p_xdbl, *p_ycomb;
    cudaGetSymbolAddress((void**)&p_patches, g_patches);
    cudaGetSymbolAddress((void**)&p_hidden,  g_hidden);
    cudaGetSymbolAddress((void**)&p_resid,   g_resid);
    cudaGetSymbolAddress((void**)&p_norm,    g_norm);
    cudaGetSymbolAddress((void**)&p_xz,      g_xz);
    cudaGetSymbolAddress((void**)&p_xc,      g_xc);
    cudaGetSymbolAddress((void**)&p_dt,      g_dt);
    cudaGetSymbolAddress((void**)&p_xpart,   g_xpart);
    cudaGetSymbolAddress((void**)&p_xdbl,    g_xdbl);
    cudaGetSymbolAddress((void**)&p_ycomb,   g_ycomb);

    k_patch_gather<<<(NPATCH * PKDIM + 255) / 256, 256>>>(x);
    k_zero<<<(LTOT * DM + 255) / 256, 256>>>(p_resid, LTOT * DM);
    // patch embed: hidden[bl, m] = patch_w[m,:] . patches[bl,:] + bias + pos + temp
    k_gemm<128, 1, 1><<<dim3(49, 3, 1), 256>>>(
        patch_w, p_patches, p_hidden, DM, LTOT, PKDIM,
        PKDIM, PKDIM, DM, 0, 0, 0, patch_b, pos, temp);

    for (int ly = 0; ly < DEPTH; ly++) {
        k_prenorm<<<LTOT, 128>>>(norm_w + ly * DM);

        // in_proj: xz[e, bl] = W[e,:] . norm[bl,:]
        k_gemm<128, 1, 0><<<dim3(49, 12, 1), 256>>>(
            in_proj + (long)ly * 2 * DI * DM, p_norm, p_xz,
            2 * DI, LTOT, DM, DM, DM, LTOT, 0, 0, 0,
            nullptr, nullptr, nullptr);

        {
            dim3 g((DI * LTOT + 255) / 256, 2);
            k_conv<<<g, 256>>>(conv_w + (long)ly * DI * 4, conv_b + (long)ly * DI,
                               conv_wb + (long)ly * DI * 4, conv_bb + (long)ly * DI);
        }

        for (int dir = 0; dir < 2; dir++) {
            const float* xpw = (dir ? xproj_wb : xproj_w) + (long)ly * 56 * DI;
            // split-K=4 (slices of 192)
            k_gemm<64, 0, 0><<<dim3(49, 1, 4), 256>>>(
                xpw, p_xc + (long)dir * DI * LTOT, p_xpart + (long)dir * 4 * 56 * LTOT,
                56, LTOT, 192, DI, LTOT, LTOT,
                192, (long)192 * LTOT, (long)56 * LTOT,
                nullptr, nullptr, nullptr);
        }
        k_xpred<<<(2 * 56 * LTOT + 255) / 256, 256>>>();

        for (int dir = 0; dir < 2; dir++) {
            const float* dw = (dir ? dt_wb : dt_w) + (long)ly * DI * DTR;
            const float* db = (dir ? dt_bb : dt_b) + (long)ly * DI;
            k_gemm<128, 0, 2><<<dim3(49, 6, 1), 256>>>(
                dw, p_xdbl + (long)dir * 56 * LTOT, p_dt + (long)dir * DI * LTOT,
                DI, LTOT, DTR, DTR, LTOT, LTOT, 0, 0, 0,
                db, nullptr, nullptr);
        }

        k_bc_t<<<(2 * BATCHSZ * LSEQ * DST + 255) / 256, 256>>>();
        k_scan<<<192, 256>>>(A_log + (long)ly * DI * DST, A_logb + (long)ly * DI * DST);
        k_combine<<<(DI * LTOT + 255) / 256, 256>>>(Dp + (long)ly * DI, Dpb + (long)ly * DI);

        // out_proj: hidden[bl, o] = W[o,:] . ycomb[:, bl]
        k_gemm<128, 0, 3><<<dim3(49, 3, 1), 256>>>(
            out_proj + (long)ly * DM * DI, p_ycomb, p_hidden,
            DM, LTOT, DI, DI, LTOT, DM, 0, 0, 0,
            nullptr, nullptr, nullptr);
    }

    k_final<<<LTOT, 128>>>(norm_f, (float*)d_out);
}